// round 1
// baseline (speedup 1.0000x reference)
#include <cuda_runtime.h>
#include <math.h>

#define BSZ   16384
#define DIM   512
#define KNUM  8192
#define BM    64
#define BN    128
#define BKK   16
#define NTHR  256
#define TM    4
#define TN    8
#define NEG_SLOPE 0.01f

// ---- scratch (static device globals; no allocations allowed) ----
__device__ float g_esq[KNUM];
__device__ float g_H[(size_t)BSZ * DIM];      // 32 MB hidden activations
__device__ int   g_melidx[BSZ];
__device__ float g_loss[BSZ];
__device__ float g_match[BSZ];

// ============================================================
// ||e_k||^2 per codebook row
// ============================================================
__global__ void esq_kernel(const float* __restrict__ E) {
    int row  = blockIdx.x * (blockDim.x >> 5) + (threadIdx.x >> 5);
    int lane = threadIdx.x & 31;
    const float* e = E + (size_t)row * DIM;
    float s = 0.f;
    for (int c = lane; c < DIM; c += 32) { float v = e[c]; s = fmaf(v, v, s); }
    #pragma unroll
    for (int o = 16; o; o >>= 1) s += __shfl_xor_sync(0xffffffffu, s, o);
    if (lane == 0) g_esq[row] = s;
}

// ============================================================
// Shared GEMM tile: acc[TM][TN] = A(64 x 512) * B(128 x 512)^T  (one col-tile)
// A rows at Ag (row-major, stride DIM), B rows at Bg (row-major, stride DIM).
// Ends with __syncthreads() so smem is safe to reuse immediately after.
// ============================================================
__device__ __forceinline__ void gemm_tile(
    const float* __restrict__ Ag,
    const float* __restrict__ Bg,
    float (*As)[BM + 1],
    float (*Bs)[BN + 4],
    float acc[TM][TN],
    int tid)
{
    const int a_r = tid >> 2, a_c = (tid & 3) << 2;   // A loads: 64 rows x 16 k
    const int b_r = tid >> 1, b_c = (tid & 1) << 3;   // B loads: 128 rows x 16 k
    const int rbase = (tid >> 4) * TM;
    const int cbase = (tid & 15) * TN;

    #pragma unroll
    for (int i = 0; i < TM; i++)
        #pragma unroll
        for (int j = 0; j < TN; j++) acc[i][j] = 0.f;

    // stage chunk 0 into registers
    float4 aR  = *(const float4*)(Ag + (size_t)a_r * DIM + a_c);
    float4 bR0 = *(const float4*)(Bg + (size_t)b_r * DIM + b_c);
    float4 bR1 = *(const float4*)(Bg + (size_t)b_r * DIM + b_c + 4);

    for (int kd = 0; kd < DIM; kd += BKK) {
        // commit staged chunk to smem (transposed: [k][row/col])
        As[a_c + 0][a_r] = aR.x; As[a_c + 1][a_r] = aR.y;
        As[a_c + 2][a_r] = aR.z; As[a_c + 3][a_r] = aR.w;
        Bs[b_c + 0][b_r] = bR0.x; Bs[b_c + 1][b_r] = bR0.y;
        Bs[b_c + 2][b_r] = bR0.z; Bs[b_c + 3][b_r] = bR0.w;
        Bs[b_c + 4][b_r] = bR1.x; Bs[b_c + 5][b_r] = bR1.y;
        Bs[b_c + 6][b_r] = bR1.z; Bs[b_c + 7][b_r] = bR1.w;
        __syncthreads();

        int kn = kd + BKK;
        if (kn < DIM) {  // prefetch next chunk, overlapped with compute below
            aR  = *(const float4*)(Ag + (size_t)a_r * DIM + kn + a_c);
            bR0 = *(const float4*)(Bg + (size_t)b_r * DIM + kn + b_c);
            bR1 = *(const float4*)(Bg + (size_t)b_r * DIM + kn + b_c + 4);
        }

        #pragma unroll
        for (int kk = 0; kk < BKK; kk++) {
            float aa[TM];
            aa[0] = As[kk][rbase + 0];
            aa[1] = As[kk][rbase + 1];
            aa[2] = As[kk][rbase + 2];
            aa[3] = As[kk][rbase + 3];
            float4 bv0 = *(const float4*)&Bs[kk][cbase];
            float4 bv1 = *(const float4*)&Bs[kk][cbase + 4];
            float bb[TN] = {bv0.x, bv0.y, bv0.z, bv0.w,
                            bv1.x, bv1.y, bv1.z, bv1.w};
            #pragma unroll
            for (int i = 0; i < TM; i++)
                #pragma unroll
                for (int j = 0; j < TN; j++)
                    acc[i][j] = fmaf(aa[i], bb[j], acc[i][j]);
        }
        __syncthreads();
    }
}

// ============================================================
// H = leakyrelu(Xeeg * W1^T + b1)   -> g_H
// ============================================================
__global__ void __launch_bounds__(NTHR)
h_kernel(const float* __restrict__ X, const float* __restrict__ W1,
         const float* __restrict__ b1)
{
    __shared__ __align__(16) float As[BKK][BM + 1];
    __shared__ __align__(16) float Bs[BKK][BN + 4];

    const int tid  = threadIdx.x;
    const int row0 = blockIdx.x * BM;
    const int col0 = blockIdx.y * BN;
    const int rbase = (tid >> 4) * TM;
    const int cbase = (tid & 15) * TN;

    float acc[TM][TN];
    gemm_tile(X + (size_t)row0 * DIM, W1 + (size_t)col0 * DIM, As, Bs, acc, tid);

    float bb[TN];
    #pragma unroll
    for (int j = 0; j < TN; j++) bb[j] = b1[col0 + cbase + j];

    #pragma unroll
    for (int i = 0; i < TM; i++) {
        float v[TN];
        #pragma unroll
        for (int j = 0; j < TN; j++) {
            float h = acc[i][j] + bb[j];
            v[j] = (h >= 0.f) ? h : NEG_SLOPE * h;
        }
        float* dst = g_H + (size_t)(row0 + rbase + i) * DIM + col0 + cbase;
        *(float4*)(dst)     = make_float4(v[0], v[1], v[2], v[3]);
        *(float4*)(dst + 4) = make_float4(v[4], v[5], v[6], v[7]);
    }
}

// ============================================================
// mel argmin: per row argmin_k (||e_k||^2 - 2 x.e_k), fused GEMM + argmin.
// One block owns 64 rows and sweeps all K -> no cross-block reduction.
// ============================================================
__global__ void __launch_bounds__(NTHR)
mel_kernel(const float* __restrict__ X, const float* __restrict__ E)
{
    __shared__ __align__(16) float As[BKK][BM + 1];
    __shared__ __align__(16) float Bs[BKK][BN + 4];
    __shared__ float sval[BM][16];
    __shared__ int   sidx[BM][16];

    const int tid  = threadIdx.x;
    const int row0 = blockIdx.x * BM;
    const int rbase = (tid >> 4) * TM;
    const int cbase = (tid & 15) * TN;
    const int tx = tid & 15;

    float bestv[TM];
    int   besti[TM];
    #pragma unroll
    for (int i = 0; i < TM; i++) { bestv[i] = INFINITY; besti[i] = 0; }

    const float* Ag = X + (size_t)row0 * DIM;
    float acc[TM][TN];

    for (int kt = 0; kt < KNUM / BN; kt++) {
        const int col0 = kt * BN;
        gemm_tile(Ag, E + (size_t)col0 * DIM, As, Bs, acc, tid);

        float eq[TN];
        #pragma unroll
        for (int j = 0; j < TN; j++) eq[j] = g_esq[col0 + cbase + j];

        #pragma unroll
        for (int i = 0; i < TM; i++)
            #pragma unroll
            for (int j = 0; j < TN; j++) {
                float d = eq[j] - 2.f * acc[i][j];
                if (d < bestv[i]) { bestv[i] = d; besti[i] = col0 + cbase + j; }
            }
    }

    #pragma unroll
    for (int i = 0; i < TM; i++) {
        sval[rbase + i][tx] = bestv[i];
        sidx[rbase + i][tx] = besti[i];
    }
    __syncthreads();

    if (tid < BM) {
        float bv = sval[tid][0]; int bi = sidx[tid][0];
        #pragma unroll
        for (int t = 1; t < 16; t++) {
            float v = sval[tid][t]; int ix = sidx[tid][t];
            if (v < bv || (v == bv && ix < bi)) { bv = v; bi = ix; }
        }
        g_melidx[row0 + tid] = bi;
    }
}

// ============================================================
// logits = H * W2^T + b2, fused per-row: argmax, online logsumexp,
// target-logit grab at mel_idx. Emits per-row loss and match flag.
// ============================================================
__global__ void __launch_bounds__(NTHR)
logits_kernel(const float* __restrict__ W2, const float* __restrict__ b2)
{
    __shared__ __align__(16) float As[BKK][BM + 1];
    __shared__ __align__(16) float Bs[BKK][BN + 4];
    __shared__ float rm [BM][16];
    __shared__ float rs [BM][16];
    __shared__ float rav[BM][16];
    __shared__ int   rai[BM][16];
    __shared__ float rtg[BM];

    const int tid  = threadIdx.x;
    const int row0 = blockIdx.x * BM;
    const int rbase = (tid >> 4) * TM;
    const int cbase = (tid & 15) * TN;
    const int tx = tid & 15;

    int mi[TM];
    #pragma unroll
    for (int i = 0; i < TM; i++) mi[i] = g_melidx[row0 + rbase + i];

    float m[TM], s[TM], av[TM], tg[TM];
    int   ai[TM], tf[TM];
    #pragma unroll
    for (int i = 0; i < TM; i++) {
        m[i] = -INFINITY; s[i] = 0.f; av[i] = -INFINITY;
        ai[i] = 0; tg[i] = 0.f; tf[i] = 0;
    }

    const float* Ag = g_H + (size_t)row0 * DIM;
    float acc[TM][TN];

    for (int kt = 0; kt < KNUM / BN; kt++) {
        const int col0 = kt * BN;
        gemm_tile(Ag, W2 + (size_t)col0 * DIM, As, Bs, acc, tid);

        float bb[TN];
        #pragma unroll
        for (int j = 0; j < TN; j++) bb[j] = b2[col0 + cbase + j];

        #pragma unroll
        for (int i = 0; i < TM; i++)
            #pragma unroll
            for (int j = 0; j < TN; j++) {
                float x = acc[i][j] + bb[j];
                int col = col0 + cbase + j;
                if (x > av[i]) { av[i] = x; ai[i] = col; }  // first-max semantics
                float mn = fmaxf(m[i], x);
                s[i] = s[i] * __expf(m[i] - mn) + __expf(x - mn);
                m[i] = mn;
                if (col == mi[i]) { tg[i] = x; tf[i] = 1; }
            }
    }

    #pragma unroll
    for (int i = 0; i < TM; i++) {
        int r = rbase + i;
        rm[r][tx] = m[i]; rs[r][tx] = s[i];
        rav[r][tx] = av[i]; rai[r][tx] = ai[i];
        if (tf[i]) rtg[r] = tg[i];   // exactly one writer per row over full K sweep
    }
    __syncthreads();

    if (tid < BM) {
        int r = tid;
        float mt = rm[r][0];
        #pragma unroll
        for (int t = 1; t < 16; t++) mt = fmaxf(mt, rm[r][t]);
        float st = 0.f;
        #pragma unroll
        for (int t = 0; t < 16; t++) st += rs[r][t] * __expf(rm[r][t] - mt);
        float bv = rav[r][0]; int bi = rai[r][0];
        #pragma unroll
        for (int t = 1; t < 16; t++) {
            float v = rav[r][t]; int ix = rai[r][t];
            if (v > bv || (v == bv && ix < bi)) { bv = v; bi = ix; }
        }
        float lse = mt + logf(st);
        int row = row0 + r;
        g_loss[row]  = lse - rtg[r];
        g_match[row] = (bi == g_melidx[row]) ? 1.f : 0.f;
    }
}

// ============================================================
// Final mean reduction -> out[0]=loss, out[1]=acc_rate
// ============================================================
__global__ void reduce_kernel(float* __restrict__ out) {
    __shared__ float sl[1024];
    __shared__ float sa[1024];
    int tid = threadIdx.x;
    float a = 0.f, b = 0.f;
    for (int i = tid; i < BSZ; i += 1024) { a += g_loss[i]; b += g_match[i]; }
    sl[tid] = a; sa[tid] = b;
    __syncthreads();
    for (int o = 512; o; o >>= 1) {
        if (tid < o) { sl[tid] += sl[tid + o]; sa[tid] += sa[tid + o]; }
        __syncthreads();
    }
    if (tid == 0) {
        out[0] = sl[0] / (float)BSZ;
        out[1] = sa[0] / (float)BSZ;
    }
}

// ============================================================
extern "C" void kernel_launch(void* const* d_in, const int* in_sizes, int n_in,
                              void* d_out, int out_size)
{
    (void)in_sizes; (void)n_in; (void)out_size;
    const float* eeg = (const float*)d_in[0];
    const float* mel = (const float*)d_in[1];
    const float* emb = (const float*)d_in[2];
    const float* W1  = (const float*)d_in[3];
    const float* b1  = (const float*)d_in[4];
    const float* W2  = (const float*)d_in[5];
    const float* b2  = (const float*)d_in[6];
    float* out = (float*)d_out;

    esq_kernel<<<KNUM / 8, 256>>>(emb);
    h_kernel<<<dim3(BSZ / BM, DIM / BN), NTHR>>>(eeg, W1, b1);
    mel_kernel<<<BSZ / BM, NTHR>>>(mel, emb);
    logits_kernel<<<BSZ / BM, NTHR>>>(W2, b2);
    reduce_kernel<<<1, 1024>>>(out);
}

// round 2
// speedup vs baseline: 4.7866x; 4.7866x over previous
#include <cuda_runtime.h>
#include <math.h>
#include <stdint.h>

#define BSZ   16384
#define DIM   512
#define KNUM  8192
#define NEG_SLOPE 0.01f

// ---- scratch (static device globals) ----
__device__ float g_esq[KNUM];
__device__ float g_H[(size_t)BSZ * DIM];   // fp32 hidden, 32 MB
__device__ int   g_meli1[BSZ], g_meli2[BSZ];
__device__ int   g_logi1[BSZ], g_logi2[BSZ];
__device__ float g_lse[BSZ];
__device__ float g_loss[BSZ], g_match[BSZ];

// ============================================================
// ||e_k||^2
// ============================================================
__global__ void esq_kernel(const float* __restrict__ E) {
    int row  = blockIdx.x * (blockDim.x >> 5) + (threadIdx.x >> 5);
    int lane = threadIdx.x & 31;
    const float* e = E + (size_t)row * DIM;
    float s = 0.f;
    for (int c = lane; c < DIM; c += 32) { float v = e[c]; s = fmaf(v, v, s); }
    #pragma unroll
    for (int o = 16; o; o >>= 1) s += __shfl_xor_sync(0xffffffffu, s, o);
    if (lane == 0) g_esq[row] = s;
}

// ============================================================
// fp32 SIMT GEMM for H (accuracy-critical, small: 17 GFLOP)
// ============================================================
__device__ __forceinline__ void gemm_tile_f32(
    const float* __restrict__ Ag, const float* __restrict__ Bg,
    float (*As)[65], float (*Bs)[132], float acc[4][8], int tid)
{
    const int a_r = tid >> 2, a_c = (tid & 3) << 2;
    const int b_r = tid >> 1, b_c = (tid & 1) << 3;
    const int rbase = (tid >> 4) * 4;
    const int cbase = (tid & 15) * 8;

    #pragma unroll
    for (int i = 0; i < 4; i++)
        #pragma unroll
        for (int j = 0; j < 8; j++) acc[i][j] = 0.f;

    float4 aR  = *(const float4*)(Ag + (size_t)a_r * DIM + a_c);
    float4 bR0 = *(const float4*)(Bg + (size_t)b_r * DIM + b_c);
    float4 bR1 = *(const float4*)(Bg + (size_t)b_r * DIM + b_c + 4);

    for (int kd = 0; kd < DIM; kd += 16) {
        As[a_c + 0][a_r] = aR.x; As[a_c + 1][a_r] = aR.y;
        As[a_c + 2][a_r] = aR.z; As[a_c + 3][a_r] = aR.w;
        Bs[b_c + 0][b_r] = bR0.x; Bs[b_c + 1][b_r] = bR0.y;
        Bs[b_c + 2][b_r] = bR0.z; Bs[b_c + 3][b_r] = bR0.w;
        Bs[b_c + 4][b_r] = bR1.x; Bs[b_c + 5][b_r] = bR1.y;
        Bs[b_c + 6][b_r] = bR1.z; Bs[b_c + 7][b_r] = bR1.w;
        __syncthreads();

        int kn = kd + 16;
        if (kn < DIM) {
            aR  = *(const float4*)(Ag + (size_t)a_r * DIM + kn + a_c);
            bR0 = *(const float4*)(Bg + (size_t)b_r * DIM + kn + b_c);
            bR1 = *(const float4*)(Bg + (size_t)b_r * DIM + kn + b_c + 4);
        }
        #pragma unroll
        for (int kk = 0; kk < 16; kk++) {
            float aa[4];
            aa[0] = As[kk][rbase + 0]; aa[1] = As[kk][rbase + 1];
            aa[2] = As[kk][rbase + 2]; aa[3] = As[kk][rbase + 3];
            float4 bv0 = *(const float4*)&Bs[kk][cbase];
            float4 bv1 = *(const float4*)&Bs[kk][cbase + 4];
            float bb[8] = {bv0.x, bv0.y, bv0.z, bv0.w, bv1.x, bv1.y, bv1.z, bv1.w};
            #pragma unroll
            for (int i = 0; i < 4; i++)
                #pragma unroll
                for (int j = 0; j < 8; j++)
                    acc[i][j] = fmaf(aa[i], bb[j], acc[i][j]);
        }
        __syncthreads();
    }
}

__global__ void __launch_bounds__(256)
h_kernel(const float* __restrict__ X, const float* __restrict__ W1,
         const float* __restrict__ b1)
{
    __shared__ __align__(16) float As[16][65];
    __shared__ __align__(16) float Bs[16][132];

    const int tid  = threadIdx.x;
    const int row0 = blockIdx.x * 64;
    const int col0 = blockIdx.y * 128;
    const int rbase = (tid >> 4) * 4;
    const int cbase = (tid & 15) * 8;

    float acc[4][8];
    gemm_tile_f32(X + (size_t)row0 * DIM, W1 + (size_t)col0 * DIM, As, Bs, acc, tid);

    float bb[8];
    #pragma unroll
    for (int j = 0; j < 8; j++) bb[j] = b1[col0 + cbase + j];

    #pragma unroll
    for (int i = 0; i < 4; i++) {
        float v[8];
        #pragma unroll
        for (int j = 0; j < 8; j++) {
            float h = acc[i][j] + bb[j];
            v[j] = (h >= 0.f) ? h : NEG_SLOPE * h;
        }
        float* dst = g_H + (size_t)(row0 + rbase + i) * DIM + col0 + cbase;
        *(float4*)(dst)     = make_float4(v[0], v[1], v[2], v[3]);
        *(float4*)(dst + 4) = make_float4(v[4], v[5], v[6], v[7]);
    }
}

// ============================================================
// TF32 tensor-core GEMM machinery (m16n8k8)
// ============================================================
#define TM_  128
#define TN_  128
#define TK_  32
#define SROW 36                       // padded smem row stride (floats)
#define STAGE_F (TM_*SROW + TN_*SROW) // 9216 floats per stage
#define NSTAGE 3
#define SMEM_BYTES (NSTAGE * STAGE_F * 4)
#define NKCH (DIM / TK_)              // 16 k-chunks

__device__ __forceinline__ void mma_tf32(float* d, const unsigned* a, const unsigned* b) {
    asm volatile(
        "mma.sync.aligned.m16n8k8.row.col.f32.tf32.tf32.f32 "
        "{%0,%1,%2,%3},{%4,%5,%6,%7},{%8,%9},{%0,%1,%2,%3};"
        : "+f"(d[0]), "+f"(d[1]), "+f"(d[2]), "+f"(d[3])
        : "r"(a[0]), "r"(a[1]), "r"(a[2]), "r"(a[3]), "r"(b[0]), "r"(b[1]));
}

__device__ __forceinline__ void cp16(float* dst, const float* src) {
    unsigned d = (unsigned)__cvta_generic_to_shared(dst);
    asm volatile("cp.async.cg.shared.global [%0], [%1], 16;" :: "r"(d), "l"(src));
}

__device__ __forceinline__ void load_tile(float* sA, float* sB,
                                          const float* Ag, const float* Bg,
                                          int kb, int tid)
{
    #pragma unroll
    for (int it = 0; it < 4; it++) {
        int f  = tid + it * 256;          // 0..1023
        int r  = f >> 3;
        int c4 = (f & 7) << 2;
        cp16(sA + r * SROW + c4, Ag + (size_t)r * DIM + kb + c4);
        cp16(sB + r * SROW + c4, Bg + (size_t)r * DIM + kb + c4);
    }
    asm volatile("cp.async.commit_group;" ::: "memory");
}

__device__ __forceinline__ void compute_stage(const float* sA, const float* sB,
                                              float acc[4][4][4],
                                              int wm, int wn, int lr, int lq)
{
    #pragma unroll
    for (int k8 = 0; k8 < 4; k8++) {
        const int kk = k8 * 8;
        unsigned a[4][4], b[4][2];
        #pragma unroll
        for (int mi = 0; mi < 4; mi++) {
            const float* ap = sA + (wm * 64 + mi * 16 + lr) * SROW + kk + lq;
            a[mi][0] = __float_as_uint(ap[0]);
            a[mi][1] = __float_as_uint(ap[8 * SROW]);
            a[mi][2] = __float_as_uint(ap[4]);
            a[mi][3] = __float_as_uint(ap[8 * SROW + 4]);
        }
        #pragma unroll
        for (int ni = 0; ni < 4; ni++) {
            const float* bp = sB + (wn * 32 + ni * 8 + lr) * SROW + kk + lq;
            b[ni][0] = __float_as_uint(bp[0]);
            b[ni][1] = __float_as_uint(bp[4]);
        }
        #pragma unroll
        for (int mi = 0; mi < 4; mi++)
            #pragma unroll
            for (int ni = 0; ni < 4; ni++)
                mma_tf32(acc[mi][ni], a[mi], b[ni]);
    }
}

// run full K=512 over one 128x128 tile with 3-stage cp.async pipeline
__device__ __forceinline__ void gemm_tile_tc(const float* Ag, const float* Bg,
                                             float* sm, float acc[4][4][4],
                                             int tid, int wm, int wn, int lr, int lq)
{
    #pragma unroll
    for (int mi = 0; mi < 4; mi++)
        #pragma unroll
        for (int ni = 0; ni < 4; ni++)
            #pragma unroll
            for (int j = 0; j < 4; j++) acc[mi][ni][j] = 0.f;

    __syncthreads();  // buffers free (prev tile fully consumed)
    load_tile(sm + 0 * STAGE_F, sm + 0 * STAGE_F + TM_ * SROW, Ag, Bg, 0, tid);
    load_tile(sm + 1 * STAGE_F, sm + 1 * STAGE_F + TM_ * SROW, Ag, Bg, TK_, tid);

    for (int kt = 0; kt < NKCH; kt++) {
        if (kt < NKCH - 1) asm volatile("cp.async.wait_group 1;" ::: "memory");
        else               asm volatile("cp.async.wait_group 0;" ::: "memory");
        __syncthreads();
        const float* buf = sm + (kt % NSTAGE) * STAGE_F;
        compute_stage(buf, buf + TM_ * SROW, acc, wm, wn, lr, lq);
        if (kt + 2 < NKCH) {
            float* nb = sm + ((kt + 2) % NSTAGE) * STAGE_F;
            load_tile(nb, nb + TM_ * SROW, Ag, Bg, (kt + 2) * TK_, tid);
        }
    }
}

// top-2 insertion (min), with index tiebreak + dedupe
__device__ __forceinline__ void ins_min(float v, int i, float& v1, int& i1, float& v2, int& i2) {
    if (v < v1 || (v == v1 && i < i1)) {
        if (i != i1) { v2 = v1; i2 = i1; }
        v1 = v; i1 = i;
    } else if (i != i1 && (v < v2 || (v == v2 && i < i2))) {
        v2 = v; i2 = i;
    }
}
__device__ __forceinline__ void ins_max(float v, int i, float& v1, int& i1, float& v2, int& i2) {
    if (v > v1 || (v == v1 && i < i1)) {
        if (i != i1) { v2 = v1; i2 = i1; }
        v1 = v; i1 = i;
    } else if (i != i1 && (v > v2 || (v == v2 && i < i2))) {
        v2 = v; i2 = i;
    }
}

// ============================================================
// mel: TF32 GEMM + fused top-2 argmin of (||e||^2 - 2 x.e)
// ============================================================
__global__ void __launch_bounds__(256, 1)
mel_mma_kernel(const float* __restrict__ X, const float* __restrict__ E)
{
    extern __shared__ float sm[];
    const int tid = threadIdx.x, w = tid >> 5, lane = tid & 31;
    const int wm = w >> 2, wn = w & 3, lr = lane >> 2, lq = lane & 3;
    const int row0 = blockIdx.x * TM_;
    const float* Ag = X + (size_t)row0 * DIM;

    float v1[8], v2[8]; int i1[8], i2[8];
    #pragma unroll
    for (int s = 0; s < 8; s++) { v1[s] = INFINITY; v2[s] = INFINITY; i1[s] = 0x7fffffff; i2[s] = 0x7fffffff; }

    float acc[4][4][4];
    for (int nt = 0; nt < KNUM / TN_; nt++) {
        const float* Bg = E + (size_t)nt * TN_ * DIM;
        gemm_tile_tc(Ag, Bg, sm, acc, tid, wm, wn, lr, lq);

        float eq[4][2];
        #pragma unroll
        for (int ni = 0; ni < 4; ni++)
            #pragma unroll
            for (int cc = 0; cc < 2; cc++)
                eq[ni][cc] = __ldg(&g_esq[nt * TN_ + wn * 32 + ni * 8 + lq * 2 + cc]);

        #pragma unroll
        for (int mi = 0; mi < 4; mi++)
            #pragma unroll
            for (int h = 0; h < 2; h++) {
                const int st = mi * 2 + h;
                #pragma unroll
                for (int ni = 0; ni < 4; ni++)
                    #pragma unroll
                    for (int cc = 0; cc < 2; cc++) {
                        float d = fmaf(-2.f, acc[mi][ni][h * 2 + cc], eq[ni][cc]);
                        int col = nt * TN_ + wn * 32 + ni * 8 + lq * 2 + cc;
                        if (d < v1[st]) { v2[st] = v1[st]; i2[st] = i1[st]; v1[st] = d; i1[st] = col; }
                        else if (d < v2[st]) { v2[st] = d; i2[st] = col; }
                    }
            }
    }

    __syncthreads();
    float* v1s = sm; float* v2s = sm + 2048;
    int* i1s = (int*)(sm + 4096); int* i2s = (int*)(sm + 6144);
    const int slot = wn * 4 + lq;
    #pragma unroll
    for (int mi = 0; mi < 4; mi++)
        #pragma unroll
        for (int h = 0; h < 2; h++) {
            int r = wm * 64 + mi * 16 + lr + h * 8;
            int st = mi * 2 + h;
            v1s[r * 16 + slot] = v1[st]; v2s[r * 16 + slot] = v2[st];
            i1s[r * 16 + slot] = i1[st]; i2s[r * 16 + slot] = i2[st];
        }
    __syncthreads();
    if (tid < TM_) {
        float bv1 = INFINITY, bv2 = INFINITY; int bi1 = 0x7fffffff, bi2 = 0x7fffffff;
        #pragma unroll
        for (int s = 0; s < 16; s++) {
            ins_min(v1s[tid * 16 + s], i1s[tid * 16 + s], bv1, bi1, bv2, bi2);
            ins_min(v2s[tid * 16 + s], i2s[tid * 16 + s], bv1, bi1, bv2, bi2);
        }
        g_meli1[row0 + tid] = bi1;
        g_meli2[row0 + tid] = bi2;
    }
}

// ============================================================
// logits: TF32 GEMM + fused top-2 argmax + online logsumexp
// ============================================================
__global__ void __launch_bounds__(256, 1)
logits_mma_kernel(const float* __restrict__ W2, const float* __restrict__ b2)
{
    extern __shared__ float sm[];
    const int tid = threadIdx.x, w = tid >> 5, lane = tid & 31;
    const int wm = w >> 2, wn = w & 3, lr = lane >> 2, lq = lane & 3;
    const int row0 = blockIdx.x * TM_;
    const float* Ag = g_H + (size_t)row0 * DIM;

    float v1[8], v2[8], m[8], s[8]; int i1[8], i2[8];
    #pragma unroll
    for (int st = 0; st < 8; st++) {
        v1[st] = -INFINITY; v2[st] = -INFINITY; i1[st] = 0x7fffffff; i2[st] = 0x7fffffff;
        m[st] = -INFINITY; s[st] = 0.f;
    }

    float acc[4][4][4];
    for (int nt = 0; nt < KNUM / TN_; nt++) {
        const float* Bg = W2 + (size_t)nt * TN_ * DIM;
        gemm_tile_tc(Ag, Bg, sm, acc, tid, wm, wn, lr, lq);

        float bb[4][2];
        #pragma unroll
        for (int ni = 0; ni < 4; ni++)
            #pragma unroll
            for (int cc = 0; cc < 2; cc++)
                bb[ni][cc] = __ldg(&b2[nt * TN_ + wn * 32 + ni * 8 + lq * 2 + cc]);

        #pragma unroll
        for (int mi = 0; mi < 4; mi++)
            #pragma unroll
            for (int h = 0; h < 2; h++) {
                const int st = mi * 2 + h;
                float x8[8];
                float mloc = -INFINITY;
                #pragma unroll
                for (int ni = 0; ni < 4; ni++)
                    #pragma unroll
                    for (int cc = 0; cc < 2; cc++) {
                        float x = acc[mi][ni][h * 2 + cc] + bb[ni][cc];
                        x8[ni * 2 + cc] = x;
                        mloc = fmaxf(mloc, x);
                        int col = nt * TN_ + wn * 32 + ni * 8 + lq * 2 + cc;
                        if (x > v1[st]) { v2[st] = v1[st]; i2[st] = i1[st]; v1[st] = x; i1[st] = col; }
                        else if (x > v2[st]) { v2[st] = x; i2[st] = col; }
                    }
                float mn = fmaxf(m[st], mloc);
                float ss = 0.f;
                #pragma unroll
                for (int e = 0; e < 8; e++) ss += __expf(x8[e] - mn);
                s[st] = fmaf(s[st], __expf(m[st] - mn), ss);
                m[st] = mn;
            }
    }

    __syncthreads();
    float* v1s = sm;                 float* v2s = sm + 2048;
    int*   i1s = (int*)(sm + 4096);  int*   i2s = (int*)(sm + 6144);
    float* ms  = sm + 8192;          float* ss  = sm + 10240;
    const int slot = wn * 4 + lq;
    #pragma unroll
    for (int mi = 0; mi < 4; mi++)
        #pragma unroll
        for (int h = 0; h < 2; h++) {
            int r = wm * 64 + mi * 16 + lr + h * 8;
            int st = mi * 2 + h;
            v1s[r * 16 + slot] = v1[st]; v2s[r * 16 + slot] = v2[st];
            i1s[r * 16 + slot] = i1[st]; i2s[r * 16 + slot] = i2[st];
            ms[r * 16 + slot] = m[st];   ss[r * 16 + slot] = s[st];
        }
    __syncthreads();
    if (tid < TM_) {
        float bv1 = -INFINITY, bv2 = -INFINITY; int bi1 = 0x7fffffff, bi2 = 0x7fffffff;
        float M = -INFINITY;
        #pragma unroll
        for (int k = 0; k < 16; k++) {
            ins_max(v1s[tid * 16 + k], i1s[tid * 16 + k], bv1, bi1, bv2, bi2);
            ins_max(v2s[tid * 16 + k], i2s[tid * 16 + k], bv1, bi1, bv2, bi2);
            M = fmaxf(M, ms[tid * 16 + k]);
        }
        float S = 0.f;
        #pragma unroll
        for (int k = 0; k < 16; k++) S += ss[tid * 16 + k] * __expf(ms[tid * 16 + k] - M);
        g_logi1[row0 + tid] = bi1;
        g_logi2[row0 + tid] = bi2;
        g_lse[row0 + tid]   = M + logf(S);
    }
}

// ============================================================
// fp32 refine: exact re-evaluation of top-2 candidates per row
// ============================================================
__device__ __forceinline__ float dot512(const float* __restrict__ a,
                                        const float* __restrict__ b, int lane)
{
    float s = 0.f;
    #pragma unroll
    for (int t = 0; t < 4; t++) {
        float4 x = *(const float4*)(a + (lane + 32 * t) * 4);
        float4 y = *(const float4*)(b + (lane + 32 * t) * 4);
        s = fmaf(x.x, y.x, s); s = fmaf(x.y, y.y, s);
        s = fmaf(x.z, y.z, s); s = fmaf(x.w, y.w, s);
    }
    #pragma unroll
    for (int o = 16; o; o >>= 1) s += __shfl_xor_sync(0xffffffffu, s, o);
    return s;
}

__global__ void __launch_bounds__(256)
refine_kernel(const float* __restrict__ Xmel, const float* __restrict__ E,
              const float* __restrict__ W2,  const float* __restrict__ b2)
{
    const int warp = threadIdx.x >> 5, lane = threadIdx.x & 31;
    const int row = blockIdx.x * 8 + warp;
    if (row >= BSZ) return;

    const float* xr = Xmel + (size_t)row * DIM;
    const float* hr = g_H  + (size_t)row * DIM;

    // mel argmin (exact fp32)
    int mi1 = g_meli1[row], mi2 = g_meli2[row];
    float d1 = g_esq[mi1] - 2.f * dot512(xr, E + (size_t)mi1 * DIM, lane);
    float d2 = g_esq[mi2] - 2.f * dot512(xr, E + (size_t)mi2 * DIM, lane);
    int mel_idx = (d1 < d2 || (d1 == d2 && mi1 < mi2)) ? mi1 : mi2;

    // eeg argmax (exact fp32)
    int j1 = g_logi1[row], j2 = g_logi2[row];
    float l1 = dot512(hr, W2 + (size_t)j1 * DIM, lane) + b2[j1];
    float l2 = dot512(hr, W2 + (size_t)j2 * DIM, lane) + b2[j2];
    int eeg_idx = (l1 > l2 || (l1 == l2 && j1 < j2)) ? j1 : j2;

    // target logit (exact fp32)
    float t = dot512(hr, W2 + (size_t)mel_idx * DIM, lane) + b2[mel_idx];

    if (lane == 0) {
        g_loss[row]  = g_lse[row] - t;
        g_match[row] = (eeg_idx == mel_idx) ? 1.f : 0.f;
    }
}

// ============================================================
// final mean reduction
// ============================================================
__global__ void reduce_kernel(float* __restrict__ out) {
    __shared__ float sl[1024];
    __shared__ float sa[1024];
    int tid = threadIdx.x;
    float a = 0.f, b = 0.f;
    for (int i = tid; i < BSZ; i += 1024) { a += g_loss[i]; b += g_match[i]; }
    sl[tid] = a; sa[tid] = b;
    __syncthreads();
    for (int o = 512; o; o >>= 1) {
        if (tid < o) { sl[tid] += sl[tid + o]; sa[tid] += sa[tid + o]; }
        __syncthreads();
    }
    if (tid == 0) {
        out[0] = sl[0] / (float)BSZ;
        out[1] = sa[0] / (float)BSZ;
    }
}

// ============================================================
extern "C" void kernel_launch(void* const* d_in, const int* in_sizes, int n_in,
                              void* d_out, int out_size)
{
    (void)in_sizes; (void)n_in; (void)out_size;
    const float* eeg = (const float*)d_in[0];
    const float* mel = (const float*)d_in[1];
    const float* emb = (const float*)d_in[2];
    const float* W1  = (const float*)d_in[3];
    const float* b1  = (const float*)d_in[4];
    const float* W2  = (const float*)d_in[5];
    const float* b2  = (const float*)d_in[6];
    float* out = (float*)d_out;

    cudaFuncSetAttribute(mel_mma_kernel,    cudaFuncAttributeMaxDynamicSharedMemorySize, SMEM_BYTES);
    cudaFuncSetAttribute(logits_mma_kernel, cudaFuncAttributeMaxDynamicSharedMemorySize, SMEM_BYTES);

    esq_kernel<<<KNUM / 8, 256>>>(emb);
    h_kernel<<<dim3(BSZ / 64, DIM / 128), 256>>>(eeg, W1, b1);
    mel_mma_kernel<<<BSZ / TM_, 256, SMEM_BYTES>>>(mel, emb);
    logits_mma_kernel<<<BSZ / TM_, 256, SMEM_BYTES>>>(W2, b2);
    refine_kernel<<<BSZ / 8, 256>>>(mel, emb, W2, b2);
    reduce_kernel<<<1, 1024>>>(out);
}